// round 11
// baseline (speedup 1.0000x reference)
#include <cuda_runtime.h>

#define B        1024
#define NUM_VARS 2048
#define LEAVES   4096
#define LEVELS   12
#define WIDTH    4096
#define NINT     (LEVELS * WIDTH)          // 49152
#define TOTAL    (LEAVES + NINT)           // 53248

#define NTHR     512
#define BBK      8                  // batch columns per block
#define NBLK     (B / BBK)          // 128 blocks

#define PCAP     1536               // max plan nodes on the fast path
#define HSZ      4096               // hash slots (power of two)
#define VPAD     9                  // val stride (9 coprime 32 -> conflict-free)
#define XPAD     2052               // floats; 8208 B row stride (16B aligned)

// Dense-fallback value buffer (touched only if plan exceeds PCAP).
__device__ float g_dense[(size_t)NINT * B];

// ---- smem layout (bytes) ----
#define SM_PCH   0                               // int4[PCAP]   raw children  24576
#define SM_SCH   (SM_PCH + PCAP * 16)            // int2[PCAP]   sorted plan   12288
#define SM_XROW  (SM_SCH + PCAP * 8)             // float[8*XPAD]              65664
#define SM_VAL   (SM_XROW + BBK * XPAD * 4)      // float[PCAP*VPAD]           55296
#define SM_HKEY  (SM_VAL + PCAP * VPAD * 4)      // int[HSZ]                   16384
#define SM_PORIG (SM_HKEY + HSZ * 4)             // int[PCAP]                   6144
#define SM_META  (SM_PORIG + PCAP * 4)           // int[PCAP] level<<16|rank    6144
#define SM_BITS  (SM_META + PCAP * 4)            // uint[NINT/32]               6144
#define SM_HVAL  (SM_BITS + NINT / 8)            // ushort[HSZ]                 8192
#define SM_SCID  (SM_HVAL + HSZ * 2)             // ushort[PCAP]                3072
#define SM_POP   (SM_SCID + PCAP * 2)            // uchar[PCAP]                 1536
#define SM_TOTAL (SM_POP + PCAP)                 // 205,440 B

// Named barrier 2: BFS warps (0-3) + init warps (4-11) = 384 threads.
#define BAR2() asm volatile("bar.sync 2, 384;" ::: "memory")

__global__ void __launch_bounds__(NTHR, 1)
eval_all(const float* __restrict__ x,
         const int*   __restrict__ child_idx,
         const int*   __restrict__ op_type,
         float*       __restrict__ out)
{
    extern __shared__ unsigned char sm[];
    int4*           pch   = (int4*)          (sm + SM_PCH);
    int2*           sch   = (int2*)          (sm + SM_SCH);
    float*          xrow  = (float*)         (sm + SM_XROW);
    float*          val   = (float*)         (sm + SM_VAL);
    int*            hkey  = (int*)           (sm + SM_HKEY);
    int*            porig = (int*)           (sm + SM_PORIG);
    int*            meta  = (int*)           (sm + SM_META);
    unsigned int*   bits  = (unsigned int*)  (sm + SM_BITS);
    unsigned short* hval  = (unsigned short*)(sm + SM_HVAL);
    unsigned short* scid  = (unsigned short*)(sm + SM_SCID);
    unsigned char*  pop   = (unsigned char*) (sm + SM_POP);

    __shared__ int scnt, sNext, sDone, sFail;
    __shared__ int slcnt[LEVELS], soff[LEVELS + 1];

    const int tid = threadIdx.x;
    const int blk = blockIdx.x;

    if (tid < 128) {
        // ========== warps 0-3: barrier-free work-stealing BFS ==========
        BAR2();                                   // wait for init (warps 4-11)
        while (true) {
            const int i = atomicAdd(&sNext, 1);
            if (i >= PCAP) break;
            // availability / termination spin.
            // Invariant: claims are fenced before sDone++, so observing
            // sDone(d) then scnt(c) with d==c && i>=c proves quiescence.
            bool have = false, dead = false;
            do {
                const int d = *(volatile int*)&sDone;
                const int c = *(volatile int*)&scnt;
                if (i < c) have = true;
                else if (d >= c) dead = true;
                else if (*(volatile int*)&sFail) dead = true;
            } while (!have && !dead);
            if (!have) break;
            // wait for the claimer to publish the node id
            int g;
            while ((g = *(volatile int*)&porig[i]) < 0) {}
            // ---- expand entry i ----
            const int ni = g - LEAVES;
            const int4 ch = ((const int4*)child_idx)[ni];
            pch[i] = ch;
            pop[i] = (unsigned char)op_type[ni];
            const int cs[4] = {ch.x, ch.y, ch.z, ch.w};
            #pragma unroll
            for (int f = 0; f < 4; ++f) {
                const int c = cs[f];
                if (c < LEAVES) continue;
                const int ci = c - LEAVES;
                const unsigned m = 1u << (ci & 31);
                const unsigned old = atomicOr(&bits[ci >> 5], m);
                if (!(old & m)) {                          // we claimed c
                    const int cid = atomicAdd(&scnt, 1);
                    if (cid < PCAP) {
                        const int l2 = ci >> 12;           // / WIDTH
                        const int r2 = atomicAdd(&slcnt[l2], 1);
                        meta[cid] = (l2 << 16) | r2;
                        unsigned slot = ((unsigned)c * 2654435761u) & (HSZ - 1);
                        while (atomicCAS(&hkey[slot], -1, c) != -1)
                            slot = (slot + 1) & (HSZ - 1);
                        hval[slot] = (unsigned short)cid;
                        porig[cid] = c;                    // publish LAST
                    } else sFail = 1;
                }
            }
            __threadfence_block();                 // claims visible before done++
            atomicAdd(&sDone, 1);
        }
    } else if (tid < 384) {
        // ========== warps 4-11: init tables + scalars, then release ==========
        const int it = tid - 128;
        const int4 m1 = make_int4(-1, -1, -1, -1);
        const int4 z0 = make_int4(0, 0, 0, 0);
        for (int i = it; i < HSZ / 4; i += 256)        ((int4*)hkey)[i] = m1;
        for (int i = it; i < NINT / 128; i += 256)     ((int4*)bits)[i] = z0;
        for (int i = it; i < PCAP; i += 256)           porig[i] = -1;
        if (tid == 128) {
            for (int l = 0; l < LEVELS; ++l) slcnt[l] = 0;
            slcnt[LEVELS - 1] = 1;
            scnt = 1; sNext = 0; sDone = 0; sFail = 0;
            meta[0]  = ((LEVELS - 1) << 16);           // root: level 11, rank 0
            porig[0] = TOTAL - 1;                      // root = cid 0
        }
        BAR2();                                        // release BFS warps
    } else {
        // ========== warps 12-15: stage x rows into smem ==========
        for (int idx = tid - 384; idx < (BBK * NUM_VARS) / 4; idx += 128) {
            const int r  = idx >> 9;                   // /512 float4 per row
            const int c4 = idx & 511;
            const float4 v =
                ((const float4*)x)[(size_t)(blk * BBK + r) * (NUM_VARS / 4) + c4];
            *(float4*)&xrow[r * XPAD + c4 * 4] = v;
        }
    }
    __syncthreads();   // JOIN: plan + xrow complete; counters stable

    const int n = (scnt < PCAP) ? scnt : PCAP;

    if (sFail) {
        // =============== dense fallback (worst case only) ===============
        for (int l = 0; l < LEVELS; ++l) {
            for (int k = tid; k < WIDTH * BBK; k += NTHR) {
                const int w2 = k >> 3, b2 = k & 7, bg2 = blk * BBK + b2;
                const int ni = l * WIDTH + w2;
                const int4 ch = ((const int4*)child_idx)[ni];
                const int cs[4] = {ch.x, ch.y, ch.z, ch.w};
                float v[4];
                #pragma unroll
                for (int f = 0; f < 4; ++f) {
                    const int c = cs[f];
                    if (c < LEAVES) {
                        const float xv = xrow[b2 * XPAD + (c & (NUM_VARS - 1))];
                        v[f] = (c < NUM_VARS) ? xv : 1.0f - xv;
                    } else {
                        v[f] = g_dense[(size_t)(c - LEAVES) * B + bg2];
                    }
                }
                const float r = op_type[ni] ? (v[0] + v[1]) + (v[2] + v[3])
                                            : (v[0] * v[1]) * (v[2] * v[3]);
                g_dense[(size_t)ni * B + bg2] = r;
            }
            __syncthreads();
        }
        if (tid < BBK)
            out[blk * BBK + tid] = g_dense[(size_t)(NINT - 1) * B + blk * BBK + tid];
        return;
    }

    // ---- prefix offsets for level-sorted plan ----
    if (tid == 0) {
        int o = 0;
        for (int l = 0; l < LEVELS; ++l) { soff[l] = o; o += slcnt[l]; }
        soff[LEVELS] = o;
    }
    __syncthreads();

    // ---- resolution: encode + scatter entries into level order ----
    // 16-bit operand: bit15=leaf, bits0-11=leaf id or cid; op in bit14 of f0.
    for (int i = tid; i < n; i += NTHR) {
        const int4 ch = pch[i];
        const int mt = meta[i];
        const int j  = soff[mt >> 16] + (mt & 0xFFFF);
        unsigned f[4];
        const int cs[4] = {ch.x, ch.y, ch.z, ch.w};
        #pragma unroll
        for (int q = 0; q < 4; ++q) {
            const int c = cs[q];
            if (c < LEAVES) f[q] = 0x8000u | (unsigned)c;
            else {
                unsigned slot = ((unsigned)c * 2654435761u) & (HSZ - 1);
                while (hkey[slot] != c) slot = (slot + 1) & (HSZ - 1);
                f[q] = hval[slot];
            }
        }
        f[0] |= ((unsigned)pop[i] & 1u) << 14;
        sch[j]  = make_int2((int)(f[0] | (f[1] << 16)), (int)(f[2] | (f[3] << 16)));
        scid[j] = (unsigned short)i;
    }
    __syncthreads();                              // plan finalized

    // ====== forward: predecoded, 64 node-lanes x 8 batch columns ======
    const int lane = tid >> 3;                    // 0..63
    const int bb   = tid & 7;

    // Predecode up to 4 entries per lane (covers n <= 256; overflow handled
    // generically below). Leaf operand VALUES preloaded into registers.
    int   aidx[4][4];  float lvv[4][4];
    int   mop[4], mdst[4], mlev[4];
    int   myN = 0;
    #pragma unroll
    for (int q = 0; q < 4; ++q) {
        const int j = lane + (q << 6);
        if (j < n) {
            const int2 e = sch[j];
            unsigned ff0 = (unsigned)e.x & 0xFFFFu;
            const unsigned ff1 = (unsigned)e.x >> 16;
            const unsigned ff2 = (unsigned)e.y & 0xFFFFu;
            const unsigned ff3 = (unsigned)e.y >> 16;
            mop[q] = (ff0 >> 14) & 1;
            ff0 &= 0x8FFFu;
            const unsigned fs[4] = {ff0, ff1, ff2, ff3};
            #pragma unroll
            for (int t = 0; t < 4; ++t) {
                const unsigned ft = fs[t];
                if (ft & 0x8000u) {
                    const float xv = xrow[bb * XPAD + (int)(ft & 2047u)];
                    lvv[q][t] = (ft & 2048u) ? 1.0f - xv : xv;
                    aidx[q][t] = -1;
                } else {
                    aidx[q][t] = (int)(ft & 0xFFFu) * VPAD + bb;
                }
            }
            mdst[q] = (int)scid[j] * VPAD + bb;
            int lv = 0;
            while (soff[lv + 1] <= j) ++lv;
            mlev[q] = lv;
            myN = q + 1;
        }
    }

    for (int l = 0; l < LEVELS; ++l) {
        #pragma unroll
        for (int q = 0; q < 4; ++q) {
            if (q < myN && mlev[q] == l) {
                const float v0 = (aidx[q][0] >= 0) ? val[aidx[q][0]] : lvv[q][0];
                const float v1 = (aidx[q][1] >= 0) ? val[aidx[q][1]] : lvv[q][1];
                const float v2 = (aidx[q][2] >= 0) ? val[aidx[q][2]] : lvv[q][2];
                const float v3 = (aidx[q][3] >= 0) ? val[aidx[q][3]] : lvv[q][3];
                const float r = mop[q] ? (v0 + v1) + (v2 + v3)
                                       : (v0 * v1) * (v2 * v3);
                val[mdst[q]] = r;
            }
        }
        if (n > 256) {
            // generic path for entries beyond the prefetch window
            for (int j = soff[l] + lane; j < soff[l + 1]; j += 64) {
                if (j < 256) continue;
                const int2 e = sch[j];
                const unsigned f0 = (unsigned)e.x & 0xFFFFu;
                const unsigned f1 = (unsigned)e.x >> 16;
                const unsigned f2 = (unsigned)e.y & 0xFFFFu;
                const unsigned f3 = (unsigned)e.y >> 16;
                const int op = (f0 >> 14) & 1;
                #define FETCH(ff) (((ff) & 0x8000u)                               \
                    ? (((ff) & 2048u)                                             \
                        ? 1.0f - xrow[bb * XPAD + (int)((ff) & 2047u)]            \
                        :        xrow[bb * XPAD + (int)((ff) & 2047u)])           \
                    : val[(int)((ff) & 0xFFFu) * VPAD + bb])
                const float v0 = FETCH(f0 & 0x8FFFu);
                const float v1 = FETCH(f1);
                const float v2 = FETCH(f2);
                const float v3 = FETCH(f3);
                #undef FETCH
                const float r = op ? (v0 + v1) + (v2 + v3)
                                   : (v0 * v1) * (v2 * v3);
                val[(int)scid[j] * VPAD + bb] = r;
            }
        }
        __syncthreads();
    }

    if (tid < BBK) out[blk * BBK + tid] = val[tid];   // root cid = 0
}

// ---------------------------------------------------------------------------
// Launch: x (f32), child_idx (i32), op_type (i32). One kernel; capturable.
// ---------------------------------------------------------------------------
extern "C" void kernel_launch(void* const* d_in, const int* in_sizes, int n_in,
                              void* d_out, int out_size) {
    const float* x         = (const float*)d_in[0];
    const int*   child_idx = (const int*)  d_in[1];
    const int*   op_type   = (const int*)  d_in[2];
    float*       out       = (float*)d_out;

    cudaFuncSetAttribute(eval_all,
                         cudaFuncAttributeMaxDynamicSharedMemorySize, SM_TOTAL);
    eval_all<<<NBLK, NTHR, SM_TOTAL>>>(x, child_idx, op_type, out);
}